// round 11
// baseline (speedup 1.0000x reference)
#include <cuda_runtime.h>
#include <cstdint>

// Shapes (fixed):
//   x [16,512,64,64] f32 | w [16,512] | weight [512,512,3,3] | affine_w [512,512]
//   affine_b [512] | out [16,512,64,64] f32
#define NB   16
#define NC   512
#define NH   64
#define NW   64
#define NHW  4096

// -------- device scratch --------
__device__ float  g_s [NB * NC];           // modulation scale s[b,i]
__device__ float  g_w2[NC * NC];           // W2[o,i] = sum_k weight^2
__device__ float  g_d [NB * NC];           // demod d[b,o]
// A operand, fragment-permuted, tf32-rounded:
//   tile_id = (pos*4 + cb)*16 + cc   (cb = co-block 0..3, cc = ci-chunk 0..15)
//   within tile (1024 float4): widx = ((ks*2+wm)*4+im)*32 + lane
//   float4 = { W[m][k], W[m+8][k], W[m][k+4], W[m+8][k+4] },
//   m = cb*128+wm*64+im*16+(lane>>2), k-chunk base = cc*32+ks*8+(lane&3)
__device__ float4 g_wt4[9 * NC * NC / 4];

// -------- helpers --------
__device__ __forceinline__ uint32_t f2tf32(float f) {
    uint32_t r; asm("cvt.rna.tf32.f32 %0, %1;" : "=r"(r) : "f"(f)); return r;
}

__device__ __forceinline__ void mma_tf32(float* c, const uint32_t* a, const uint32_t* b) {
    asm volatile(
        "mma.sync.aligned.m16n8k8.row.col.f32.tf32.tf32.f32 "
        "{%0,%1,%2,%3}, {%4,%5,%6,%7}, {%8,%9}, {%0,%1,%2,%3};"
        : "+f"(c[0]), "+f"(c[1]), "+f"(c[2]), "+f"(c[3])
        : "r"(a[0]), "r"(a[1]), "r"(a[2]), "r"(a[3]),
          "r"(b[0]), "r"(b[1]));
}

// -------- prep kernels --------
__global__ void k_modscale(const float* __restrict__ w,
                           const float* __restrict__ aw,
                           const float* __restrict__ ab) {
    int b = blockIdx.y, warp = threadIdx.x >> 5, lane = threadIdx.x & 31;
    int i = blockIdx.x * 8 + warp;
    const float* wrow = w + b * NC;
    const float* arow = aw + i * NC;
    float sum = 0.f;
#pragma unroll
    for (int j = lane; j < NC; j += 32) sum += wrow[j] * arow[j];
#pragma unroll
    for (int off = 16; off; off >>= 1) sum += __shfl_xor_sync(0xffffffffu, sum, off);
    if (lane == 0) g_s[b * NC + i] = sum + ab[i] + 1.0f;
}

__global__ void k_w2(const float* __restrict__ weight) {
    int idx = blockIdx.x * blockDim.x + threadIdx.x;   // < 262144
    const float* p = weight + (size_t)idx * 9;
    float s = 0.f;
#pragma unroll
    for (int t = 0; t < 9; t++) s += p[t] * p[t];
    g_w2[idx] = s;
}

// fragment-permute weights into g_wt4 (one float4 per thread, coalesced stores)
__global__ void k_wtperm(const float* __restrict__ weight) {
    int fidx = blockIdx.x * blockDim.x + threadIdx.x;   // < 589824
    int widx = fidx & 1023;
    int tile = fidx >> 10;                              // 0..575
    int cc   = tile & 15;
    int tmp  = tile >> 4;
    int cb   = tmp & 3;
    int pos  = tmp >> 2;                                // 0..8
    int lane = widx & 31;
    int im   = (widx >> 5) & 3;
    int wm   = (widx >> 7) & 1;
    int ks   = widx >> 8;
    int g = lane >> 2, t = lane & 3;
    int co = cb * 128 + wm * 64 + im * 16 + g;
    int ci = cc * 32 + ks * 8 + t;
    float4 v;
    v.x = __uint_as_float(f2tf32(weight[((co    ) * NC + ci    ) * 9 + pos]));
    v.y = __uint_as_float(f2tf32(weight[((co + 8) * NC + ci    ) * 9 + pos]));
    v.z = __uint_as_float(f2tf32(weight[((co    ) * NC + ci + 4) * 9 + pos]));
    v.w = __uint_as_float(f2tf32(weight[((co + 8) * NC + ci + 4) * 9 + pos]));
    g_wt4[fidx] = v;
}

__global__ void k_demod() {
    int b = blockIdx.y, warp = threadIdx.x >> 5, lane = threadIdx.x & 31;
    int o = blockIdx.x * 8 + warp;
    const float* srow = g_s + b * NC;
    const float* w2r  = g_w2 + o * NC;
    float sum = 0.f;
#pragma unroll
    for (int j = lane; j < NC; j += 32) { float sv = srow[j]; sum += sv * sv * w2r[j]; }
#pragma unroll
    for (int off = 16; off; off >>= 1) sum += __shfl_xor_sync(0xffffffffu, sum, off);
    if (lane == 0) g_d[b * NC + o] = rsqrtf(sum + 1e-8f);
}

// -------- main conv: legacy tf32 mma.sync, fragment-vectorized smem --------
// CTA 256 thr (8 warps 2x4). Tile M=128 co x N=128 px (2 rows) x K=32 ci/iter.
// A: cp.async double-buffer of pre-permuted 16KB tiles (frag loads = LDS.128).
// B: halo of tf32(x*s) once per ci-chunk -> per-pos repack into paired float2
//    layout Bf[ks][t][n] (pitch 265) -> frag loads = LDS.64.

#define HKP  273          // halo k-pitch (floats)
#define HRP  68           // halo row pitch (floats)
#define BTS  265          // Bf t-row pitch (float2 units)
// smem floats: A 2*4096, Bf 4*4*BTS*2=8480, halo 32*HKP=8736, sS 512
#define SMEM_FLOATS (8192 + 8480 + 8736 + 512)
#define SMEM_BYTES  (SMEM_FLOATS * 4)

__device__ __forceinline__ void prefA(const float4* __restrict__ src,
                                      float* dst, int tid) {
#pragma unroll
    for (int j = 0; j < 4; j++) {
        int ch = tid + 256 * j;                 // 0..1023
        uint32_t d = (uint32_t)__cvta_generic_to_shared(dst + ch * 4);
        asm volatile("cp.async.cg.shared.global [%0], [%1], 16;"
                     :: "r"(d), "l"(src + ch));
    }
    asm volatile("cp.async.commit_group;" ::: "memory");
}

__global__ void __launch_bounds__(256, 2)
k_conv(const float* __restrict__ x, float* __restrict__ out) {
    extern __shared__ float smem[];
    float* As   = smem;                 // 2 x 4096 floats
    float* Bf   = smem + 8192;          // 8480 floats
    float* halo = smem + 8192 + 8480;   // 8736 floats
    float* sS   = halo + 8736;          // 512 floats

    const int tid  = threadIdx.x;
    const int wid  = tid >> 5;
    const int lane = tid & 31;
    const int wm   = wid >> 2;          // 0..1
    const int wn   = wid & 3;           // 0..3
    const int g    = lane >> 2;         // 0..7
    const int t    = lane & 3;          // 0..3

    const int b    = blockIdx.z;
    const int row0 = blockIdx.y * 2;
    const int cb   = blockIdx.x;        // co block (x128)

    sS[tid]       = g_s[b * NC + tid];
    sS[tid + 256] = g_s[b * NC + tid + 256];

    // prefetch A tile for it=0 (pos 0, cc 0)
    prefA(g_wt4 + ((size_t)(0 * 4 + cb) * 16 + 0) * 1024, As, tid);

    const float* xb = x + (size_t)b * NC * NHW;

    float acc[4][4][4];
#pragma unroll
    for (int im = 0; im < 4; im++)
#pragma unroll
        for (int in = 0; in < 4; in++)
#pragma unroll
            for (int q = 0; q < 4; q++) acc[im][in][q] = 0.f;

    __syncthreads();   // sS visible before halo staging

    int pos = 0, cc = 0;
#pragma unroll 1
    for (int it = 0; it < 144; ++it) {
        // ---- stage halo once per ci chunk (no one reads halo during mma) ----
        if (pos == 0) {
#pragma unroll
            for (int j = 0; j < 34; j++) {
                int idx = tid + 256 * j;           // 32*272 = 8704
                int k   = idx / 272;
                int rem = idx - k * 272;
                int r   = rem / HRP;
                int c   = rem - r * HRP;
                int xr  = row0 - 1 + r, xc = c - 1;
                float v = 0.f;
                if ((unsigned)xr < (unsigned)NH && (unsigned)xc < (unsigned)NW)
                    v = xb[((cc * 32 + k) << 12) + (xr << 6) + xc] * sS[cc * 32 + k];
                halo[k * HKP + r * HRP + c] = __uint_as_float(f2tf32(v));
            }
        }

        __syncthreads();   // #1: mma(it-1) readers done (A slot + Bf free); halo visible

        // ---- prefetch A(it+1) into the freed slot ----
        if (it + 1 < 144) {
            int np = pos + 1, ncc = cc;
            if (np == 9) { np = 0; ncc++; }
            prefA(g_wt4 + ((size_t)(np * 4 + cb) * 16 + ncc) * 1024,
                  As + ((it + 1) & 1) * 4096, tid);
        } else {
            asm volatile("cp.async.commit_group;" ::: "memory");
        }

        // ---- repack Bf[ks][t][n] = {halo[k],halo[k+4]} at shifted pixel ----
        {
            const int kh = pos / 3 - 1;
            const int kw = pos - (pos / 3) * 3 - 1;
#pragma unroll
            for (int r = 0; r < 2; r++) {
                int pid = tid + 256 * r;            // 0..511
                int ks  = pid >> 7;
                int n   = pid & 127;
                const float* hp = halo + (ks * 8) * HKP
                                + ((n >> 6) + kh + 1) * HRP + (n & 63) + kw + 1;
                float a0 = hp[0 * HKP], a1 = hp[1 * HKP], a2 = hp[2 * HKP], a3 = hp[3 * HKP];
                float a4 = hp[4 * HKP], a5 = hp[5 * HKP], a6 = hp[6 * HKP], a7 = hp[7 * HKP];
                float2* bp = (float2*)Bf + (ks * 4) * BTS + n;
                bp[0 * BTS] = make_float2(a0, a4);
                bp[1 * BTS] = make_float2(a1, a5);
                bp[2 * BTS] = make_float2(a2, a6);
                bp[3 * BTS] = make_float2(a3, a7);
            }
        }

        asm volatile("cp.async.wait_group 1;" ::: "memory");   // A(it) resident
        __syncthreads();   // #2: Bf staged + A(it) visible to all

        // ---- 4 k-steps x 16 mma ----
        {
            const float4* Ab = (const float4*)(As + (it & 1) * 4096);
#pragma unroll
            for (int ks = 0; ks < 4; ++ks) {
                float4 afv[4];
                const float4* ap = Ab + ((ks * 2 + wm) * 4) * 32 + lane;
#pragma unroll
                for (int im = 0; im < 4; im++) afv[im] = ap[im * 32];
                float2 bfv[4];
                const float2* bp = (const float2*)Bf + (ks * 4 + t) * BTS + wn * 32 + g;
#pragma unroll
                for (int in = 0; in < 4; in++) bfv[in] = bp[in * 8];
#pragma unroll
                for (int im = 0; im < 4; im++) {
                    uint32_t af[4] = { __float_as_uint(afv[im].x), __float_as_uint(afv[im].y),
                                       __float_as_uint(afv[im].z), __float_as_uint(afv[im].w) };
#pragma unroll
                    for (int in = 0; in < 4; in++) {
                        uint32_t bfr[2] = { __float_as_uint(bfv[in].x),
                                            __float_as_uint(bfv[in].y) };
                        mma_tf32(acc[im][in], af, bfr);
                    }
                }
            }
        }

        if (++pos == 9) { pos = 0; cc++; }
    }

    // ---- epilogue: scale by d[b,co], store float2 ----
    float* ob = out + (size_t)(b * NC + cb * 128) * NHW + row0 * NW;
#pragma unroll
    for (int im = 0; im < 4; im++) {
        int m0 = wm * 64 + im * 16 + g;
        float d0 = g_d[b * NC + cb * 128 + m0];
        float d1 = g_d[b * NC + cb * 128 + m0 + 8];
#pragma unroll
        for (int in = 0; in < 4; in++) {
            int n = wn * 32 + in * 8 + t * 2;
            float2 v0 = make_float2(acc[im][in][0] * d0, acc[im][in][1] * d0);
            float2 v1 = make_float2(acc[im][in][2] * d1, acc[im][in][3] * d1);
            *(float2*)(ob + (size_t)m0 * NHW + n)       = v0;
            *(float2*)(ob + (size_t)(m0 + 8) * NHW + n) = v1;
        }
    }
}

// -------- launch --------
extern "C" void kernel_launch(void* const* d_in, const int* in_sizes, int n_in,
                              void* d_out, int out_size) {
    (void)in_sizes; (void)n_in; (void)out_size;
    const float* x      = (const float*)d_in[0];
    const float* w      = (const float*)d_in[1];
    const float* weight = (const float*)d_in[2];
    const float* aw     = (const float*)d_in[3];
    const float* ab     = (const float*)d_in[4];
    float* out = (float*)d_out;

    static bool attr_set = false;
    if (!attr_set) {
        cudaFuncSetAttribute(k_conv, cudaFuncAttributeMaxDynamicSharedMemorySize,
                             SMEM_BYTES);
        attr_set = true;
    }

    k_modscale<<<dim3(64, 16), 256>>>(w, aw, ab);
    k_w2<<<1024, 256>>>(weight);
    k_wtperm<<<2304, 256>>>(weight);      // 589824 / 256
    k_demod<<<dim3(64, 16), 256>>>();
    k_conv<<<dim3(4, 32, 16), 256, SMEM_BYTES>>>(x, out);
}

// round 12
// speedup vs baseline: 1.0949x; 1.0949x over previous
#include <cuda_runtime.h>
#include <cstdint>

// Shapes (fixed):
//   x [16,512,64,64] f32 | w [16,512] | weight [512,512,3,3] | affine_w [512,512]
//   affine_b [512] | out [16,512,64,64] f32
#define NB   16
#define NC   512
#define NH   64
#define NW   64
#define NHW  4096

// -------- device scratch --------
__device__ float g_s [NB * NC];          // modulation scale s[b,i]
__device__ float g_w2[NC * NC];          // W2[o,i] = sum_k weight^2
__device__ float g_d [NB * NC];          // demod d[b,o]
__device__ float g_wt[9 * NC * NC];      // Wt[pos][ci][co], tf32-rounded

// -------- helpers --------
__device__ __forceinline__ uint32_t f2tf32(float f) {
    uint32_t r; asm("cvt.rna.tf32.f32 %0, %1;" : "=r"(r) : "f"(f)); return r;
}

__device__ __forceinline__ void mma_tf32(float* c, const uint32_t* a, const uint32_t* b) {
    asm volatile(
        "mma.sync.aligned.m16n8k8.row.col.f32.tf32.tf32.f32 "
        "{%0,%1,%2,%3}, {%4,%5,%6,%7}, {%8,%9}, {%0,%1,%2,%3};"
        : "+f"(c[0]), "+f"(c[1]), "+f"(c[2]), "+f"(c[3])
        : "r"(a[0]), "r"(a[1]), "r"(a[2]), "r"(a[3]),
          "r"(b[0]), "r"(b[1]));
}

// -------- prep kernels --------
__global__ void k_modscale(const float* __restrict__ w,
                           const float* __restrict__ aw,
                           const float* __restrict__ ab) {
    int b = blockIdx.y, warp = threadIdx.x >> 5, lane = threadIdx.x & 31;
    int i = blockIdx.x * 8 + warp;
    const float* wrow = w + b * NC;
    const float* arow = aw + i * NC;
    float sum = 0.f;
#pragma unroll
    for (int j = lane; j < NC; j += 32) sum += wrow[j] * arow[j];
#pragma unroll
    for (int off = 16; off; off >>= 1) sum += __shfl_xor_sync(0xffffffffu, sum, off);
    if (lane == 0) g_s[b * NC + i] = sum + ab[i] + 1.0f;
}

// fused: W2 sum-of-squares + transpose weights to g_wt[pos][ci][co] (tf32)
__global__ void k_wtw2(const float* __restrict__ weight) {
    int idx = blockIdx.x * blockDim.x + threadIdx.x;   // co*512 + ci, < 262144
    int co = idx >> 9, ci = idx & 511;
    const float* p = weight + (size_t)idx * 9;
    float v[9], s = 0.f;
#pragma unroll
    for (int t = 0; t < 9; t++) { v[t] = p[t]; s += v[t] * v[t]; }
    g_w2[idx] = s;
#pragma unroll
    for (int t = 0; t < 9; t++)
        g_wt[t * (NC * NC) + ci * NC + co] = __uint_as_float(f2tf32(v[t]));
}

__global__ void k_demod() {
    int b = blockIdx.y, warp = threadIdx.x >> 5, lane = threadIdx.x & 31;
    int o = blockIdx.x * 8 + warp;
    const float* srow = g_s + b * NC;
    const float* w2r  = g_w2 + o * NC;
    float sum = 0.f;
#pragma unroll
    for (int j = lane; j < NC; j += 32) { float sv = srow[j]; sum += sv * sv * w2r[j]; }
#pragma unroll
    for (int off = 16; off; off >>= 1) sum += __shfl_xor_sync(0xffffffffu, sum, off);
    if (lane == 0) g_d[b * NC + o] = rsqrtf(sum + 1e-8f);
}

// -------- main conv: legacy tf32 mma.sync, 1 sync/iter, incremental halo --------
// CTA 256 thr (8 warps, 2x4). Tile M=128 co x N=128 px (2 rows) x K=32 ci/iter.
// A: 2-slot cp.async double buffer (prefA after the barrier -> race-free).
// B: double-buffered halo of tf32(x*s); next chunk staged 5 rows/iter during
//    pos 1..7 of the current chunk; mma reads B fragments directly from halo.

#define APITCH 132                   // A k-row pitch; frag banks 4t+g conflict-free
#define ASZ    (32 * APITCH)         // 4224 floats per A slot
#define BKS    292                   // halo k-stride (292 % 32 == 4): conflict-free
#define BRS    68                    // halo row stride (4 rows x 66 used cols)
#define HSZ    (32 * BKS)            // 9344 floats per halo buffer
#define SMEM_FLOATS (2 * ASZ + 2 * HSZ + NC)
#define SMEM_BYTES  (SMEM_FLOATS * 4)   // 110592 B -> 2 CTAs/SM

__device__ __forceinline__ void prefA(const float* __restrict__ wtp, float* dstbuf,
                                      int tid) {
#pragma unroll
    for (int j = 0; j < 4; j++) {
        int idx = tid + 256 * j;           // 0..1023
        int k   = idx >> 5;                // ci row 0..31
        int c16 = idx & 31;                // 16B chunk within 512B row
        const float* src = wtp + k * NC + c16 * 4;
        uint32_t dst = (uint32_t)__cvta_generic_to_shared(dstbuf + k * APITCH + c16 * 4);
        asm volatile("cp.async.cg.shared.global [%0], [%1], 16;" :: "r"(dst), "l"(src));
    }
    asm volatile("cp.async.commit_group;" ::: "memory");
}

__global__ void __launch_bounds__(256, 2)
k_conv(const float* __restrict__ x, float* __restrict__ out) {
    extern __shared__ float smem[];
    float* As   = smem;                    // 2 x 4224
    float* halo = smem + 2 * ASZ;          // 2 x 9344
    float* sS   = smem + 2 * ASZ + 2 * HSZ;

    const int tid  = threadIdx.x;
    const int wid  = tid >> 5;
    const int lane = tid & 31;
    const int wm   = wid >> 2;             // 0..1
    const int wn   = wid & 3;              // 0..3
    const int g    = lane >> 2;            // 0..7
    const int t    = lane & 3;             // 0..3

    const int b       = blockIdx.z;
    const int row0    = blockIdx.y * 2;
    const int co_base = blockIdx.x * 128;

    sS[tid]       = g_s[b * NC + tid];
    sS[tid + 256] = g_s[b * NC + tid + 256];
    __syncthreads();                       // sS visible before any staging

    const float* xb = x + (size_t)b * NC * NHW;

    // stage halo for chunk 0 (full 34 steps)
#pragma unroll
    for (int j = 0; j < 34; j++) {
        int idx = tid + 256 * j;           // 32*272 = 8704
        int k   = idx / 272;
        int rem = idx - k * 272;
        int r   = rem / BRS;
        int c   = rem - r * BRS;
        int xr  = row0 - 1 + r, xc = c - 1;
        float v = 0.f;
        if ((unsigned)xr < (unsigned)NH && (unsigned)xc < (unsigned)NW)
            v = xb[(k << 12) + (xr << 6) + xc] * sS[k];
        halo[k * BKS + r * BRS + c] = __uint_as_float(f2tf32(v));
    }
    // prefetch A for it=0 (pos 0, chunk 0) into slot 0
    prefA(g_wt + co_base, As, tid);

    // per-thread B fragment n-offsets (n = wn*32 + in*8 + g)
    int noff[4];
#pragma unroll
    for (int in = 0; in < 4; in++) {
        int n = wn * 32 + in * 8 + g;
        noff[in] = (n >> 6) * BRS + (n & 63);
    }

    float acc[4][4][4];
#pragma unroll
    for (int im = 0; im < 4; im++)
#pragma unroll
        for (int in = 0; in < 4; in++)
#pragma unroll
            for (int q = 0; q < 4; q++) acc[im][in][q] = 0.f;

    int pos = 0, cc = 0;
#pragma unroll 1
    for (int it = 0; it < 144; ++it) {
        // ---- stage 5 rows of NEXT chunk's halo during pos 1..7 ----
        if (pos >= 1 && cc < 15) {
            float* hn = halo + ((cc + 1) & 1) * HSZ;
            const int kbase = (cc + 1) * 32;
#pragma unroll
            for (int jj = 0; jj < 5; jj++) {
                int j = (pos - 1) * 5 + jj;
                if (j < 34) {
                    int idx = tid + 256 * j;
                    int k   = idx / 272;
                    int rem = idx - k * 272;
                    int r   = rem / BRS;
                    int c   = rem - r * BRS;
                    int xr  = row0 - 1 + r, xc = c - 1;
                    float v = 0.f;
                    if ((unsigned)xr < (unsigned)NH && (unsigned)xc < (unsigned)NW)
                        v = xb[((kbase + k) << 12) + (xr << 6) + xc] * sS[kbase + k];
                    hn[k * BKS + r * BRS + c] = __uint_as_float(f2tf32(v));
                }
            }
        }

        asm volatile("cp.async.wait_group 0;" ::: "memory");   // A(it) resident
        __syncthreads();   // single barrier: A(it)+halo visible; mma(it-1) done

        // ---- prefetch A(it+1) into the other slot (safe: after barrier) ----
        if (it + 1 < 144) {
            int np = pos + 1, ncc = cc;
            if (np == 9) { np = 0; ncc++; }
            prefA(g_wt + (size_t)np * (NC * NC) + ncc * 32 * NC + co_base,
                  As + ((it + 1) & 1) * ASZ, tid);
        }

        // ---- mma block: 4 k-steps x 16 mma, frags straight from smem ----
        {
            const int kh = pos / 3 - 1;
            const int kw = pos - (pos / 3) * 3 - 1;
            const float* Ab = As + (it & 1) * ASZ;
            const float* Bb = halo + (cc & 1) * HSZ + (1 + kh) * BRS + (1 + kw);
#pragma unroll
            for (int ks = 0; ks < 4; ++ks) {
                const int krow = ks * 8 + t;
                uint32_t af[4][4];
                uint32_t bf[4][2];
#pragma unroll
                for (int im = 0; im < 4; im++) {
                    const float* p = Ab + krow * APITCH + wm * 64 + im * 16 + g;
                    af[im][0] = __float_as_uint(p[0]);
                    af[im][1] = __float_as_uint(p[8]);
                    af[im][2] = __float_as_uint(p[4 * APITCH]);
                    af[im][3] = __float_as_uint(p[4 * APITCH + 8]);
                }
#pragma unroll
                for (int in = 0; in < 4; in++) {
                    const float* p = Bb + krow * BKS + noff[in];
                    bf[in][0] = __float_as_uint(p[0]);
                    bf[in][1] = __float_as_uint(p[4 * BKS]);
                }
#pragma unroll
                for (int im = 0; im < 4; im++)
#pragma unroll
                    for (int in = 0; in < 4; in++)
                        mma_tf32(acc[im][in], af[im], bf[in]);
            }
        }

        if (++pos == 9) { pos = 0; cc++; }
    }

    // ---- epilogue: scale by d[b,co], store float2 ----
    float* ob = out + (size_t)(b * NC + co_base) * NHW + row0 * NW;
#pragma unroll
    for (int im = 0; im < 4; im++) {
        int m0 = wm * 64 + im * 16 + g;
        float d0 = g_d[b * NC + co_base + m0];
        float d1 = g_d[b * NC + co_base + m0 + 8];
#pragma unroll
        for (int in = 0; in < 4; in++) {
            int n = wn * 32 + in * 8 + t * 2;
            float2 v0 = make_float2(acc[im][in][0] * d0, acc[im][in][1] * d0);
            float2 v1 = make_float2(acc[im][in][2] * d1, acc[im][in][3] * d1);
            *(float2*)(ob + (size_t)m0 * NHW + n)       = v0;
            *(float2*)(ob + (size_t)(m0 + 8) * NHW + n) = v1;
        }
    }
}

// -------- launch --------
extern "C" void kernel_launch(void* const* d_in, const int* in_sizes, int n_in,
                              void* d_out, int out_size) {
    (void)in_sizes; (void)n_in; (void)out_size;
    const float* x      = (const float*)d_in[0];
    const float* w      = (const float*)d_in[1];
    const float* weight = (const float*)d_in[2];
    const float* aw     = (const float*)d_in[3];
    const float* ab     = (const float*)d_in[4];
    float* out = (float*)d_out;

    static bool attr_set = false;
    if (!attr_set) {
        cudaFuncSetAttribute(k_conv, cudaFuncAttributeMaxDynamicSharedMemorySize,
                             SMEM_BYTES);
        attr_set = true;
    }

    k_modscale<<<dim3(64, 16), 256>>>(w, aw, ab);
    k_wtw2<<<1024, 256>>>(weight);
    k_demod<<<dim3(64, 16), 256>>>();
    k_conv<<<dim3(4, 32, 16), 256, SMEM_BYTES>>>(x, out);
}

// round 13
// speedup vs baseline: 1.4827x; 1.3542x over previous
#include <cuda_runtime.h>
#include <cstdint>

// Shapes (fixed):
//   x [16,512,64,64] f32 | w [16,512] | weight [512,512,3,3] | affine_w [512,512]
//   affine_b [512] | out [16,512,64,64] f32
#define NB   16
#define NC   512
#define NH   64
#define NW   64
#define NHW  4096

// -------- device scratch --------
__device__ float g_s [NB * NC];          // modulation scale s[b,i]
__device__ float g_w2[NC * NC];          // W2[o,i] = sum_k weight^2
__device__ float g_d [NB * NC];          // demod d[b,o]
__device__ float g_wt[9 * NC * NC];      // Wt[pos][ci][co], tf32-rounded

// -------- helpers --------
__device__ __forceinline__ uint32_t f2tf32(float f) {
    uint32_t r; asm("cvt.rna.tf32.f32 %0, %1;" : "=r"(r) : "f"(f)); return r;
}

__device__ __forceinline__ void mma_tf32(float* c, const uint32_t* a, const uint32_t* b) {
    asm volatile(
        "mma.sync.aligned.m16n8k8.row.col.f32.tf32.tf32.f32 "
        "{%0,%1,%2,%3}, {%4,%5,%6,%7}, {%8,%9}, {%0,%1,%2,%3};"
        : "+f"(c[0]), "+f"(c[1]), "+f"(c[2]), "+f"(c[3])
        : "r"(a[0]), "r"(a[1]), "r"(a[2]), "r"(a[3]),
          "r"(b[0]), "r"(b[1]));
}

// -------- prep kernels --------
__global__ void k_modscale(const float* __restrict__ w,
                           const float* __restrict__ aw,
                           const float* __restrict__ ab) {
    int b = blockIdx.y, warp = threadIdx.x >> 5, lane = threadIdx.x & 31;
    int i = blockIdx.x * 8 + warp;
    const float* wrow = w + b * NC;
    const float* arow = aw + i * NC;
    float sum = 0.f;
#pragma unroll
    for (int j = lane; j < NC; j += 32) sum += wrow[j] * arow[j];
#pragma unroll
    for (int off = 16; off; off >>= 1) sum += __shfl_xor_sync(0xffffffffu, sum, off);
    if (lane == 0) g_s[b * NC + i] = sum + ab[i] + 1.0f;
}

// fused: W2 sum-of-squares + transpose weights to g_wt[pos][ci][co] (tf32)
__global__ void k_wtw2(const float* __restrict__ weight) {
    int idx = blockIdx.x * blockDim.x + threadIdx.x;   // co*512 + ci, < 262144
    int co = idx >> 9, ci = idx & 511;
    const float* p = weight + (size_t)idx * 9;
    float v[9], s = 0.f;
#pragma unroll
    for (int t = 0; t < 9; t++) { v[t] = p[t]; s += v[t] * v[t]; }
    g_w2[idx] = s;
#pragma unroll
    for (int t = 0; t < 9; t++)
        g_wt[t * (NC * NC) + ci * NC + co] = __uint_as_float(f2tf32(v[t]));
}

__global__ void k_demod() {
    int b = blockIdx.y, warp = threadIdx.x >> 5, lane = threadIdx.x & 31;
    int o = blockIdx.x * 8 + warp;
    const float* srow = g_s + b * NC;
    const float* w2r  = g_w2 + o * NC;
    float sum = 0.f;
#pragma unroll
    for (int j = lane; j < NC; j += 32) { float sv = srow[j]; sum += sv * sv * w2r[j]; }
#pragma unroll
    for (int off = 16; off; off >>= 1) sum += __shfl_xor_sync(0xffffffffu, sum, off);
    if (lane == 0) g_d[b * NC + o] = rsqrtf(sum + 1e-8f);
}

// -------- main conv: legacy tf32 mma.sync, cp.async halo, s folded into B frags ----
// CTA 256 thr (8 warps, 2x4). Tile M=128 co x N=128 px (2 rows) x K=32 ci/iter.
// A: 2-slot cp.async double buffer. B: double-buffered RAW-x halo staged entirely
// via 4B cp.async (zero-fill for OOB), 5 elems/thread/iter during pos 1..7.
// s[ci] applied to B fragments in registers (FMUL + cvt.rna.tf32) -> bit-identical
// numerics to the previous staging-time multiply.

#define APITCH 132                   // A k-row pitch; frag banks 4t+g conflict-free
#define ASZ    (32 * APITCH)         // 4224 floats per A slot
#define BKS    292                   // halo k-stride (292 % 32 == 4): conflict-free
#define BRS    68                    // halo row stride (4 rows x 66 used cols)
#define HSZ    (32 * BKS)            // 9344 floats per halo buffer
#define SMEM_FLOATS (2 * ASZ + 2 * HSZ + NC)
#define SMEM_BYTES  (SMEM_FLOATS * 4)   // 110592 B -> 2 CTAs/SM

__device__ __forceinline__ void prefA(const float* __restrict__ wtp, float* dstbuf,
                                      int tid) {
#pragma unroll
    for (int j = 0; j < 4; j++) {
        int idx = tid + 256 * j;           // 0..1023
        int k   = idx >> 5;                // ci row 0..31
        int c16 = idx & 31;                // 16B chunk within 512B row
        const float* src = wtp + k * NC + c16 * 4;
        uint32_t dst = (uint32_t)__cvta_generic_to_shared(dstbuf + k * APITCH + c16 * 4);
        asm volatile("cp.async.cg.shared.global [%0], [%1], 16;" :: "r"(dst), "l"(src));
    }
    asm volatile("cp.async.commit_group;" ::: "memory");
}

// stage one halo element via 4B cp.async; OOB -> zero-fill (src-size 0, clamped addr)
__device__ __forceinline__ void stage1(const float* __restrict__ xk, float* hbuf,
                                       int j, int tid, int row0) {
    int idx = tid + 256 * j;               // < 8704 = 32*272
    int k   = idx / 272;
    int rem = idx - k * 272;
    int r   = rem / BRS;
    int c   = rem - r * BRS;
    int xr  = row0 - 1 + r, xc = c - 1;
    bool ok = ((unsigned)xr < (unsigned)NH) && ((unsigned)xc < (unsigned)NW);
    int off = ok ? ((xr << 6) + xc) : 0;
    const float* src = xk + (k << 12) + off;
    uint32_t dst = (uint32_t)__cvta_generic_to_shared(hbuf + k * BKS + r * BRS + c);
    uint32_t sz  = ok ? 4u : 0u;
    asm volatile("cp.async.ca.shared.global [%0], [%1], 4, %2;"
                 :: "r"(dst), "l"(src), "r"(sz));
}

__global__ void __launch_bounds__(256, 2)
k_conv(const float* __restrict__ x, float* __restrict__ out) {
    extern __shared__ float smem[];
    float* As   = smem;                    // 2 x 4224
    float* halo = smem + 2 * ASZ;          // 2 x 9344 (raw x)
    float* sS   = smem + 2 * ASZ + 2 * HSZ;

    const int tid  = threadIdx.x;
    const int wid  = tid >> 5;
    const int lane = tid & 31;
    const int wm   = wid >> 2;             // 0..1
    const int wn   = wid & 3;              // 0..3
    const int g    = lane >> 2;            // 0..7
    const int t    = lane & 3;             // 0..3

    const int b       = blockIdx.z;
    const int row0    = blockIdx.y * 2;
    const int co_base = blockIdx.x * 128;

    sS[tid]       = g_s[b * NC + tid];
    sS[tid + 256] = g_s[b * NC + tid + 256];

    const float* xb = x + (size_t)b * NC * NHW;

    // stage halo chunk 0 (raw x, all 34 steps, fire-and-forget) + commit
#pragma unroll
    for (int j = 0; j < 34; j++) stage1(xb, halo, j, tid, row0);
    asm volatile("cp.async.commit_group;" ::: "memory");
    // prefetch A for it=0 (pos 0, chunk 0) into slot 0 (commits its own group)
    prefA(g_wt + co_base, As, tid);

    // per-thread B fragment n-offsets (n = wn*32 + in*8 + g)
    int noff[4];
#pragma unroll
    for (int in = 0; in < 4; in++) {
        int n = wn * 32 + in * 8 + g;
        noff[in] = (n >> 6) * BRS + (n & 63);
    }

    float acc[4][4][4];
#pragma unroll
    for (int im = 0; im < 4; im++)
#pragma unroll
        for (int in = 0; in < 4; in++)
#pragma unroll
            for (int q = 0; q < 4; q++) acc[im][in][q] = 0.f;

    int pos = 0, cc = 0;
#pragma unroll 1
    for (int it = 0; it < 144; ++it) {
        // ---- stage 5 elems of NEXT chunk's halo (cp.async, no stall) ----
        if (pos >= 1 && cc < 15) {
            float* hn = halo + ((cc + 1) & 1) * HSZ;
            const float* xk = xb + (size_t)((cc + 1) * 32) * NHW;
#pragma unroll
            for (int jj = 0; jj < 5; jj++) {
                int j = (pos - 1) * 5 + jj;
                if (j < 34) stage1(xk, hn, j, tid, row0);
            }
        }

        asm volatile("cp.async.wait_group 0;" ::: "memory");   // A(it)+older staging
        __syncthreads();   // single barrier: A(it)+halo visible; mma(it-1) done

        // ---- prefetch A(it+1); commits pending staging ops with it ----
        if (it + 1 < 144) {
            int np = pos + 1, ncc = cc;
            if (np == 9) { np = 0; ncc++; }
            prefA(g_wt + (size_t)np * (NC * NC) + ncc * 32 * NC + co_base,
                  As + ((it + 1) & 1) * ASZ, tid);
        }

        // ---- mma block: 4 k-steps x 16 mma; s folded into B frags ----
        {
            const int kh = pos / 3 - 1;
            const int kw = pos - (pos / 3) * 3 - 1;
            const float* Ab = As + (it & 1) * ASZ;
            const float* Bb = halo + (cc & 1) * HSZ + (1 + kh) * BRS + (1 + kw);
            const float* sbase = sS + cc * 32 + t;
            float s0[4], s4[4];
#pragma unroll
            for (int ks = 0; ks < 4; ks++) { s0[ks] = sbase[ks * 8]; s4[ks] = sbase[ks * 8 + 4]; }
#pragma unroll
            for (int ks = 0; ks < 4; ++ks) {
                const int krow = ks * 8 + t;
                uint32_t af[4][4];
#pragma unroll
                for (int im = 0; im < 4; im++) {
                    const float* p = Ab + krow * APITCH + wm * 64 + im * 16 + g;
                    af[im][0] = __float_as_uint(p[0]);
                    af[im][1] = __float_as_uint(p[8]);
                    af[im][2] = __float_as_uint(p[4 * APITCH]);
                    af[im][3] = __float_as_uint(p[4 * APITCH + 8]);
                }
                uint32_t bf[4][2];
#pragma unroll
                for (int in = 0; in < 4; in++) {
                    const float* p = Bb + krow * BKS + noff[in];
                    bf[in][0] = f2tf32(p[0] * s0[ks]);
                    bf[in][1] = f2tf32(p[4 * BKS] * s4[ks]);
                }
#pragma unroll
                for (int im = 0; im < 4; im++)
#pragma unroll
                    for (int in = 0; in < 4; in++)
                        mma_tf32(acc[im][in], af[im], bf[in]);
            }
        }

        if (++pos == 9) { pos = 0; cc++; }
    }

    // ---- epilogue: scale by d[b,co], store float2 ----
    float* ob = out + (size_t)(b * NC + co_base) * NHW + row0 * NW;
#pragma unroll
    for (int im = 0; im < 4; im++) {
        int m0 = wm * 64 + im * 16 + g;
        float d0 = g_d[b * NC + co_base + m0];
        float d1 = g_d[b * NC + co_base + m0 + 8];
#pragma unroll
        for (int in = 0; in < 4; in++) {
            int n = wn * 32 + in * 8 + t * 2;
            float2 v0 = make_float2(acc[im][in][0] * d0, acc[im][in][1] * d0);
            float2 v1 = make_float2(acc[im][in][2] * d1, acc[im][in][3] * d1);
            *(float2*)(ob + (size_t)m0 * NHW + n)       = v0;
            *(float2*)(ob + (size_t)(m0 + 8) * NHW + n) = v1;
        }
    }
}

// -------- launch --------
extern "C" void kernel_launch(void* const* d_in, const int* in_sizes, int n_in,
                              void* d_out, int out_size) {
    (void)in_sizes; (void)n_in; (void)out_size;
    const float* x      = (const float*)d_in[0];
    const float* w      = (const float*)d_in[1];
    const float* weight = (const float*)d_in[2];
    const float* aw     = (const float*)d_in[3];
    const float* ab     = (const float*)d_in[4];
    float* out = (float*)d_out;

    static bool attr_set = false;
    if (!attr_set) {
        cudaFuncSetAttribute(k_conv, cudaFuncAttributeMaxDynamicSharedMemorySize,
                             SMEM_BYTES);
        attr_set = true;
    }

    k_modscale<<<dim3(64, 16), 256>>>(w, aw, ab);
    k_wtw2<<<1024, 256>>>(weight);
    k_demod<<<dim3(64, 16), 256>>>();
    k_conv<<<dim3(4, 32, 16), 256, SMEM_BYTES>>>(x, out);
}

// round 14
// speedup vs baseline: 1.6582x; 1.1184x over previous
#include <cuda_runtime.h>
#include <cstdint>

// Shapes (fixed):
//   x [16,512,64,64] f32 | w [16,512] | weight [512,512,3,3] | affine_w [512,512]
//   affine_b [512] | out [16,512,64,64] f32
#define NB   16
#define NC   512
#define NH   64
#define NW   64
#define NHW  4096

// -------- device scratch --------
__device__ float g_s [NB * NC];          // modulation scale s[b,i]
__device__ float g_w2[NC * NC];          // W2[o,i] = sum_k weight^2
__device__ float g_d [NB * NC];          // demod d[b,o]
__device__ float g_wt[9 * NC * NC];      // Wt[pos][ci][co], tf32-rounded

// -------- helpers --------
__device__ __forceinline__ uint32_t f2tf32(float f) {
    uint32_t r; asm("cvt.rna.tf32.f32 %0, %1;" : "=r"(r) : "f"(f)); return r;
}

__device__ __forceinline__ void mma_tf32(float* c, const uint32_t* a, const uint32_t* b) {
    asm volatile(
        "mma.sync.aligned.m16n8k8.row.col.f32.tf32.tf32.f32 "
        "{%0,%1,%2,%3}, {%4,%5,%6,%7}, {%8,%9}, {%0,%1,%2,%3};"
        : "+f"(c[0]), "+f"(c[1]), "+f"(c[2]), "+f"(c[3])
        : "r"(a[0]), "r"(a[1]), "r"(a[2]), "r"(a[3]),
          "r"(b[0]), "r"(b[1]));
}

// -------- prep kernels --------
__global__ void k_modscale(const float* __restrict__ w,
                           const float* __restrict__ aw,
                           const float* __restrict__ ab) {
    int b = blockIdx.y, warp = threadIdx.x >> 5, lane = threadIdx.x & 31;
    int i = blockIdx.x * 8 + warp;
    const float* wrow = w + b * NC;
    const float* arow = aw + i * NC;
    float sum = 0.f;
#pragma unroll
    for (int j = lane; j < NC; j += 32) sum += wrow[j] * arow[j];
#pragma unroll
    for (int off = 16; off; off >>= 1) sum += __shfl_xor_sync(0xffffffffu, sum, off);
    if (lane == 0) g_s[b * NC + i] = sum + ab[i] + 1.0f;
}

// fused: W2 sum-of-squares + transpose weights to g_wt[pos][ci][co] (tf32)
__global__ void k_wtw2(const float* __restrict__ weight) {
    int idx = blockIdx.x * blockDim.x + threadIdx.x;   // co*512 + ci, < 262144
    int co = idx >> 9, ci = idx & 511;
    const float* p = weight + (size_t)idx * 9;
    float v[9], s = 0.f;
#pragma unroll
    for (int t = 0; t < 9; t++) { v[t] = p[t]; s += v[t] * v[t]; }
    g_w2[idx] = s;
#pragma unroll
    for (int t = 0; t < 9; t++)
        g_wt[t * (NC * NC) + ci * NC + co] = __uint_as_float(f2tf32(v[t]));
}

__global__ void k_demod() {
    int b = blockIdx.y, warp = threadIdx.x >> 5, lane = threadIdx.x & 31;
    int o = blockIdx.x * 8 + warp;
    const float* srow = g_s + b * NC;
    const float* w2r  = g_w2 + o * NC;
    float sum = 0.f;
#pragma unroll
    for (int j = lane; j < NC; j += 32) { float sv = srow[j]; sum += sv * sv * w2r[j]; }
#pragma unroll
    for (int off = 16; off; off >>= 1) sum += __shfl_xor_sync(0xffffffffu, sum, off);
    if (lane == 0) g_d[b * NC + o] = rsqrtf(sum + 1e-8f);
}

// -------- main conv: legacy tf32 mma.sync, 64x64 warp tiles (min smem dup) ------
// CTA 128 thr (4 warps, 2x2). Tile M=128 co x N=128 px (2 rows) x K=32 ci/iter.
// Warp tile 64x64 -> A and B each read only 2x from smem (was 4x/2x): LDS/mma
// drops 1.5 -> 1.0.  A: 2-slot cp.async double buffer.  B: double-buffered RAW-x
// halo staged via 4B cp.async (zero-fill OOB), s folded into B frags in registers.

#define APITCH 132                   // A k-row pitch; frag banks 4t+g conflict-free
#define ASZ    (32 * APITCH)         // 4224 floats per A slot
#define BKS    292                   // halo k-stride (292 % 32 == 4): conflict-free
#define BRS    68                    // halo row stride (4 rows x 66 used cols)
#define HSZ    (32 * BKS)            // 9344 floats per halo buffer
#define SMEM_FLOATS (2 * ASZ + 2 * HSZ + NC)
#define SMEM_BYTES  (SMEM_FLOATS * 4)   // 110592 B -> 2 CTAs/SM

__device__ __forceinline__ void prefA(const float* __restrict__ wtp, float* dstbuf,
                                      int tid) {
#pragma unroll
    for (int j = 0; j < 8; j++) {
        int idx = tid + 128 * j;           // 0..1023
        int k   = idx >> 5;                // ci row 0..31
        int c16 = idx & 31;                // 16B chunk within 512B row
        const float* src = wtp + k * NC + c16 * 4;
        uint32_t dst = (uint32_t)__cvta_generic_to_shared(dstbuf + k * APITCH + c16 * 4);
        asm volatile("cp.async.cg.shared.global [%0], [%1], 16;" :: "r"(dst), "l"(src));
    }
    asm volatile("cp.async.commit_group;" ::: "memory");
}

// stage one halo element via 4B cp.async; OOB -> zero-fill (src-size 0)
__device__ __forceinline__ void stage1(const float* __restrict__ xk, float* hbuf,
                                       int j, int tid, int row0) {
    int idx = tid + 128 * j;               // < 8704 = 32*272
    int k   = idx / 272;
    int rem = idx - k * 272;
    int r   = rem / BRS;
    int c   = rem - r * BRS;
    int xr  = row0 - 1 + r, xc = c - 1;
    bool ok = ((unsigned)xr < (unsigned)NH) && ((unsigned)xc < (unsigned)NW);
    int off = ok ? ((xr << 6) + xc) : 0;
    const float* src = xk + (k << 12) + off;
    uint32_t dst = (uint32_t)__cvta_generic_to_shared(hbuf + k * BKS + r * BRS + c);
    uint32_t sz  = ok ? 4u : 0u;
    asm volatile("cp.async.ca.shared.global [%0], [%1], 4, %2;"
                 :: "r"(dst), "l"(src), "r"(sz));
}

__global__ void __launch_bounds__(128, 2)
k_conv(const float* __restrict__ x, float* __restrict__ out) {
    extern __shared__ float smem[];
    float* As   = smem;                    // 2 x 4224
    float* halo = smem + 2 * ASZ;          // 2 x 9344 (raw x)
    float* sS   = smem + 2 * ASZ + 2 * HSZ;

    const int tid  = threadIdx.x;
    const int wid  = tid >> 5;
    const int lane = tid & 31;
    const int wm   = wid >> 1;             // 0..1 (64 M-rows each)
    const int wn   = wid & 1;              // 0..1 (64 N-cols each)
    const int g    = lane >> 2;            // 0..7
    const int t    = lane & 3;             // 0..3

    const int b       = blockIdx.z;
    const int row0    = blockIdx.y * 2;
    const int co_base = blockIdx.x * 128;

#pragma unroll
    for (int j = 0; j < 4; j++) sS[tid + 128 * j] = g_s[b * NC + tid + 128 * j];

    const float* xb = x + (size_t)b * NC * NHW;

    // stage halo chunk 0 (raw x, fire-and-forget) + commit
#pragma unroll
    for (int j = 0; j < 68; j++) stage1(xb, halo, j, tid, row0);
    asm volatile("cp.async.commit_group;" ::: "memory");
    // prefetch A for it=0 (pos 0, chunk 0) into slot 0 (commits its own group)
    prefA(g_wt + co_base, As, tid);

    // per-thread B fragment n-offsets (n = wn*64 + in*8 + g)
    int noff[8];
#pragma unroll
    for (int in = 0; in < 8; in++) {
        int n = wn * 64 + in * 8 + g;
        noff[in] = (n >> 6) * BRS + (n & 63);
    }

    float acc[4][8][4];
#pragma unroll
    for (int im = 0; im < 4; im++)
#pragma unroll
        for (int in = 0; in < 8; in++)
#pragma unroll
            for (int q = 0; q < 4; q++) acc[im][in][q] = 0.f;

    int pos = 0, cc = 0;
#pragma unroll 1
    for (int it = 0; it < 144; ++it) {
        // ---- stage 10 elems of NEXT chunk's halo (cp.async, no stall) ----
        if (pos >= 1 && cc < 15) {
            float* hn = halo + ((cc + 1) & 1) * HSZ;
            const float* xk = xb + (size_t)((cc + 1) * 32) * NHW;
#pragma unroll
            for (int jj = 0; jj < 10; jj++) {
                int j = (pos - 1) * 10 + jj;
                if (j < 68) stage1(xk, hn, j, tid, row0);
            }
        }

        asm volatile("cp.async.wait_group 0;" ::: "memory");   // A(it)+older staging
        __syncthreads();   // single barrier: A(it)+halo visible; mma(it-1) done

        // ---- prefetch A(it+1); commits pending staging ops with it ----
        if (it + 1 < 144) {
            int np = pos + 1, ncc = cc;
            if (np == 9) { np = 0; ncc++; }
            prefA(g_wt + (size_t)np * (NC * NC) + ncc * 32 * NC + co_base,
                  As + ((it + 1) & 1) * ASZ, tid);
        }

        // ---- mma block: 4 k-steps x 32 mma; s folded into B frags ----
        {
            const int kh = pos / 3 - 1;
            const int kw = pos - (pos / 3) * 3 - 1;
            const float* Ab = As + (it & 1) * ASZ;
            const float* Bb = halo + (cc & 1) * HSZ + (1 + kh) * BRS + (1 + kw);
            const float* sbase = sS + cc * 32 + t;
#pragma unroll
            for (int ks = 0; ks < 4; ++ks) {
                const int krow = ks * 8 + t;
                uint32_t af[4][4];
#pragma unroll
                for (int im = 0; im < 4; im++) {
                    const float* p = Ab + krow * APITCH + wm * 64 + im * 16 + g;
                    af[im][0] = __float_as_uint(p[0]);
                    af[im][1] = __float_as_uint(p[8]);
                    af[im][2] = __float_as_uint(p[4 * APITCH]);
                    af[im][3] = __float_as_uint(p[4 * APITCH + 8]);
                }
                const float s0 = sbase[ks * 8];
                const float s4 = sbase[ks * 8 + 4];
                uint32_t bf[8][2];
#pragma unroll
                for (int in = 0; in < 8; in++) {
                    const float* p = Bb + krow * BKS + noff[in];
                    bf[in][0] = f2tf32(p[0] * s0);
                    bf[in][1] = f2tf32(p[4 * BKS] * s4);
                }
#pragma unroll
                for (int im = 0; im < 4; im++)
#pragma unroll
                    for (int in = 0; in < 8; in++)
                        mma_tf32(acc[im][in], af[im], bf[in]);
            }
        }

        if (++pos == 9) { pos = 0; cc++; }
    }

    // ---- epilogue: scale by d[b,co], store float2 ----
    float* ob = out + (size_t)(b * NC + co_base) * NHW + row0 * NW;
#pragma unroll
    for (int im = 0; im < 4; im++) {
        int m0 = wm * 64 + im * 16 + g;
        float d0 = g_d[b * NC + co_base + m0];
        float d1 = g_d[b * NC + co_base + m0 + 8];
#pragma unroll
        for (int in = 0; in < 8; in++) {
            int n = wn * 64 + in * 8 + t * 2;
            float2 v0 = make_float2(acc[im][in][0] * d0, acc[im][in][1] * d0);
            float2 v1 = make_float2(acc[im][in][2] * d1, acc[im][in][3] * d1);
            *(float2*)(ob + (size_t)m0 * NHW + n)       = v0;
            *(float2*)(ob + (size_t)(m0 + 8) * NHW + n) = v1;
        }
    }
}

// -------- launch --------
extern "C" void kernel_launch(void* const* d_in, const int* in_sizes, int n_in,
                              void* d_out, int out_size) {
    (void)in_sizes; (void)n_in; (void)out_size;
    const float* x      = (const float*)d_in[0];
    const float* w      = (const float*)d_in[1];
    const float* weight = (const float*)d_in[2];
    const float* aw     = (const float*)d_in[3];
    const float* ab     = (const float*)d_in[4];
    float* out = (float*)d_out;

    static bool attr_set = false;
    if (!attr_set) {
        cudaFuncSetAttribute(k_conv, cudaFuncAttributeMaxDynamicSharedMemorySize,
                             SMEM_BYTES);
        attr_set = true;
    }

    k_modscale<<<dim3(64, 16), 256>>>(w, aw, ab);
    k_wtw2<<<1024, 256>>>(weight);
    k_demod<<<dim3(64, 16), 256>>>();
    k_conv<<<dim3(4, 32, 16), 128, SMEM_BYTES>>>(x, out);
}